// round 4
// baseline (speedup 1.0000x reference)
#include <cuda_runtime.h>

// Problem constants
#define H 4096
#define W 4096
#define EPSV 0.005f

// Tile config: 96x96 output, 128x128 halo region (radius 16 = 2 box filters of r=8)
#define T 96
#define REGN 128
#define STRIDE 129            // +1 pad: conflict-free row-strided access
#define NTHREADS 1024
#define INV17 (1.0f/17.0f)

// 64 MB luma scratch (device global: allocation-free per harness rules)
__device__ float g_Y[(size_t)H * W];

__device__ __forceinline__ int refl(int p) {
    p = (p < 0) ? -p : p;                 // 'reflect' mode: -1 -> 1
    return (p > H - 1) ? (2 * (H - 1) - p) : p;
}

// ---------------------------------------------------------------------------
// Kernel 1: Rec.709 luma, 4 pixels per thread via 3x float4 loads
// ---------------------------------------------------------------------------
__global__ void luma_kernel(const float* __restrict__ x) {
    int i = blockIdx.x * blockDim.x + threadIdx.x;   // quad-pixel index
    const float4* xv = (const float4*)x;
    float4 f0 = xv[3 * i + 0];
    float4 f1 = xv[3 * i + 1];
    float4 f2 = xv[3 * i + 2];
    const float cr = 0.2126f, cg = 0.7152f, cb = 0.0722f;
    float4 y;
    y.x = cr * f0.x + cg * f0.y + cb * f0.z;
    y.y = cr * f0.w + cg * f1.x + cb * f1.y;
    y.z = cr * f1.z + cg * f1.w + cb * f2.x;
    y.w = cr * f2.y + cg * f2.z + cb * f2.w;
    ((float4*)g_Y)[i] = y;
}

// ---------------------------------------------------------------------------
// Kernel 2: fully fused guided filter per 96x96 tile.
// Smem buffers (each 128x129 f32):
//   A: Y -> a -> mean_a -> scale
//   B: hbox(Y) -> hbox(a) -> hbox(b)
//   C: hbox(Y^2) -> b -> mean_b
// ---------------------------------------------------------------------------
__global__ void __launch_bounds__(NTHREADS, 1)
fused_kernel(const float* __restrict__ x, float* __restrict__ out) {
    extern __shared__ float smem[];
    float* A = smem;
    float* B = A + REGN * STRIDE;
    float* C = B + REGN * STRIDE;

    const int tid = threadIdx.x;
    const int gx0 = blockIdx.x * T - 16;
    const int gy0 = blockIdx.y * T - 16;

    // ---- stage 0: load Y halo (reflect-indexed), coalesced ----
    #pragma unroll
    for (int k = 0; k < 16; k++) {
        int idx = k * NTHREADS + tid;          // 0..16383
        int ry = idx >> 7;
        int rx = idx & 127;
        int gy = refl(gy0 + ry);
        int gx = refl(gx0 + rx);
        A[ry * STRIDE + rx] = g_Y[(size_t)gy * W + gx];
    }
    __syncthreads();

    // ---- stash center Y in registers (A gets overwritten later) ----
    float Yreg[9];
    #pragma unroll
    for (int k = 0; k < 9; k++) {
        int px = k * NTHREADS + tid;           // 0..9215
        int r = px / 96;
        int c = px - r * 96;
        Yreg[k] = A[(16 + r) * STRIDE + (16 + c)];
    }

    // ---- stage 1: horizontal box of Y and Y^2 (running sums) ----
    // 128 rows x 8 segments of 14 cols; valid output cols 8..119
    {
        int row = tid & 127, seg = tid >> 7;
        int c0 = 8 + seg * 14;
        const float* ar = A + row * STRIDE;
        float* br = B + row * STRIDE;
        float* cr2 = C + row * STRIDE;
        float s1 = 0.f, s2 = 0.f;
        #pragma unroll
        for (int k = -8; k <= 8; k++) { float v = ar[c0 + k]; s1 += v; s2 += v * v; }
        br[c0] = s1 * INV17; cr2[c0] = s2 * INV17;
        #pragma unroll
        for (int i = 1; i < 14; i++) {
            float vo = ar[c0 + i - 9], vn = ar[c0 + i + 8];
            s1 += vn - vo;
            s2 += vn * vn - vo * vo;
            br[c0 + i] = s1 * INV17; cr2[c0 + i] = s2 * INV17;
        }
    }
    __syncthreads();

    // ---- stage 3a: vertical box -> mean_I, mean_II -> a into A ----
    // cols 8..119 active x 8 segments of 14 rows; rows 8..119
    {
        int col = tid & 127, seg = tid >> 7;
        if (col >= 8 && col < 120) {
            int r0 = 8 + seg * 14;
            float s1 = 0.f, s2 = 0.f;
            #pragma unroll
            for (int k = -8; k <= 8; k++) {
                s1 += B[(r0 + k) * STRIDE + col];
                s2 += C[(r0 + k) * STRIDE + col];
            }
            #pragma unroll
            for (int i = 0; i < 14; i++) {
                int r = r0 + i;
                float mI = s1 * INV17, mII = s2 * INV17;
                float var = mII - mI * mI;
                float a = var / (var + EPSV);
                A[r * STRIDE + col] = a;
                if (i < 13) {
                    s1 += B[(r + 9) * STRIDE + col] - B[(r - 8) * STRIDE + col];
                    s2 += C[(r + 9) * STRIDE + col] - C[(r - 8) * STRIDE + col];
                }
            }
        }
    }
    __syncthreads();

    // ---- stage 3b: vertical box of B again -> b = mean_I - a*mean_I into C ----
    {
        int col = tid & 127, seg = tid >> 7;
        if (col >= 8 && col < 120) {
            int r0 = 8 + seg * 14;
            float s1 = 0.f;
            #pragma unroll
            for (int k = -8; k <= 8; k++) s1 += B[(r0 + k) * STRIDE + col];
            #pragma unroll
            for (int i = 0; i < 14; i++) {
                int r = r0 + i;
                float mI = s1 * INV17;
                float a = A[r * STRIDE + col];
                C[r * STRIDE + col] = mI - a * mI;
                if (i < 13)
                    s1 += B[(r + 9) * STRIDE + col] - B[(r - 8) * STRIDE + col];
            }
        }
    }
    __syncthreads();

    // ---- stage 4a: horizontal box of a (A) -> B; rows 8..119, cols 16..111 ----
    {
        int row = tid & 127, seg = tid >> 7;
        if (row >= 8 && row < 120) {
            int c0 = 16 + seg * 12;
            const float* ar = A + row * STRIDE;
            float* br = B + row * STRIDE;
            float s = 0.f;
            #pragma unroll
            for (int k = -8; k <= 8; k++) s += ar[c0 + k];
            #pragma unroll
            for (int i = 0; i < 12; i++) {
                br[c0 + i] = s * INV17;
                if (i < 11) s += ar[c0 + i + 9] - ar[c0 + i - 8];
            }
        }
    }
    __syncthreads();

    // ---- stage 4b: vertical box of B -> mean_a into A center ----
    {
        int col = tid & 127, seg = tid >> 7;
        if (col >= 16 && col < 112) {
            int r0 = 16 + seg * 12;
            float s = 0.f;
            #pragma unroll
            for (int k = -8; k <= 8; k++) s += B[(r0 + k) * STRIDE + col];
            #pragma unroll
            for (int i = 0; i < 12; i++) {
                A[(r0 + i) * STRIDE + col] = s * INV17;
                if (i < 11)
                    s += B[(r0 + i + 9) * STRIDE + col] - B[(r0 + i - 8) * STRIDE + col];
            }
        }
    }
    __syncthreads();

    // ---- stage 4c: horizontal box of b (C) -> B ----
    {
        int row = tid & 127, seg = tid >> 7;
        if (row >= 8 && row < 120) {
            int c0 = 16 + seg * 12;
            const float* cr2 = C + row * STRIDE;
            float* br = B + row * STRIDE;
            float s = 0.f;
            #pragma unroll
            for (int k = -8; k <= 8; k++) s += cr2[c0 + k];
            #pragma unroll
            for (int i = 0; i < 12; i++) {
                br[c0 + i] = s * INV17;
                if (i < 11) s += cr2[c0 + i + 9] - cr2[c0 + i - 8];
            }
        }
    }
    __syncthreads();

    // ---- stage 4d: vertical box of B -> mean_b into C center ----
    {
        int col = tid & 127, seg = tid >> 7;
        if (col >= 16 && col < 112) {
            int r0 = 16 + seg * 12;
            float s = 0.f;
            #pragma unroll
            for (int k = -8; k <= 8; k++) s += B[(r0 + k) * STRIDE + col];
            #pragma unroll
            for (int i = 0; i < 12; i++) {
                C[(r0 + i) * STRIDE + col] = s * INV17;
                if (i < 11)
                    s += B[(r0 + i + 9) * STRIDE + col] - B[(r0 + i - 8) * STRIDE + col];
            }
        }
    }
    __syncthreads();

    // ---- stage 5a: scale = (mean_a*Y + mean_b)/max(Y,1e-6) into A center ----
    #pragma unroll
    for (int k = 0; k < 9; k++) {
        int px = k * NTHREADS + tid;
        int r = px / 96;
        int c = px - r * 96;
        int off = (16 + r) * STRIDE + (16 + c);
        float ma = A[off];
        float mb = C[off];
        float y = Yreg[k];
        float s = (ma * y + mb) / fmaxf(y, 1e-6f);
        A[off] = s;
    }
    __syncthreads();

    // ---- stage 5b: apply to x, fully coalesced flat-float loop ----
    const int outy0 = blockIdx.y * T;
    const int outx0 = blockIdx.x * T;
    #pragma unroll
    for (int k = 0; k < 27; k++) {
        int f = k * NTHREADS + tid;            // 0..27647 (96*96*3)
        int r = f / 288;
        int rem = f - r * 288;
        int c = rem / 3;
        int ch = rem - c * 3;
        int gy = outy0 + r, gx = outx0 + c;
        if (gy < H && gx < W) {
            size_t addr = ((size_t)gy * W + gx) * 3 + ch;
            float s = A[(16 + r) * STRIDE + (16 + c)];
            float v = x[addr] * s;
            out[addr] = fminf(fmaxf(v, 0.f), 1.f);
        }
    }
}

// ---------------------------------------------------------------------------
extern "C" void kernel_launch(void* const* d_in, const int* in_sizes, int n_in,
                              void* d_out, int out_size) {
    const float* x = (const float*)d_in[0];
    float* out = (float*)d_out;

    const int smem_bytes = 3 * REGN * STRIDE * (int)sizeof(float);  // 198144
    cudaFuncSetAttribute(fused_kernel,
                         cudaFuncAttributeMaxDynamicSharedMemorySize, smem_bytes);

    // K1: luma (4 px / thread)
    luma_kernel<<<(H * W / 4) / 256, 256>>>(x);

    // K2: fused guided filter, 43x43 tiles of 96x96
    dim3 grid((W + T - 1) / T, (H + T - 1) / T);
    fused_kernel<<<grid, NTHREADS, smem_bytes>>>(x, out);
}

// round 5
// speedup vs baseline: 1.0005x; 1.0005x over previous
#include <cuda_runtime.h>

// Problem constants
#define H 4096
#define W 4096
#define EPSV 0.005f

// Tile config: 96x96 output, 128x128 halo region (radius 16 = 2 box filters of r=8)
#define T 96
#define REGN 128
#define STRIDE 129            // +1 pad: conflict-free row-strided access
#define NTHREADS 1024
#define INV17 (1.0f/17.0f)

// 64 MB luma scratch (device global: allocation-free per harness rules)
__device__ float g_Y[(size_t)H * W];

__device__ __forceinline__ int refl(int p) {
    p = (p < 0) ? -p : p;                 // 'reflect' mode: -1 -> 1
    return (p > H - 1) ? (2 * (H - 1) - p) : p;
}

// ---------------------------------------------------------------------------
// Kernel 1: Rec.709 luma, 4 pixels per thread via 3x float4 loads
// ---------------------------------------------------------------------------
__global__ void luma_kernel(const float* __restrict__ x) {
    int i = blockIdx.x * blockDim.x + threadIdx.x;   // quad-pixel index
    const float4* xv = (const float4*)x;
    float4 f0 = xv[3 * i + 0];
    float4 f1 = xv[3 * i + 1];
    float4 f2 = xv[3 * i + 2];
    const float cr = 0.2126f, cg = 0.7152f, cb = 0.0722f;
    float4 y;
    y.x = cr * f0.x + cg * f0.y + cb * f0.z;
    y.y = cr * f0.w + cg * f1.x + cb * f1.y;
    y.z = cr * f1.z + cg * f1.w + cb * f2.x;
    y.w = cr * f2.y + cg * f2.z + cb * f2.w;
    ((float4*)g_Y)[i] = y;
}

// ---------------------------------------------------------------------------
// Kernel 2: fully fused guided filter per 96x96 tile.
// Smem buffers (each 128x129 f32):
//   A: Y -> a -> mean_a -> scale
//   B: hbox(Y) -> hbox(a) -> hbox(b)
//   C: hbox(Y^2) -> b -> mean_b
// ---------------------------------------------------------------------------
__global__ void __launch_bounds__(NTHREADS, 1)
fused_kernel(const float* __restrict__ x, float* __restrict__ out) {
    extern __shared__ float smem[];
    float* A = smem;
    float* B = A + REGN * STRIDE;
    float* C = B + REGN * STRIDE;

    const int tid = threadIdx.x;
    const int gx0 = blockIdx.x * T - 16;
    const int gy0 = blockIdx.y * T - 16;

    // ---- stage 0: load Y halo (reflect-indexed), coalesced ----
    #pragma unroll
    for (int k = 0; k < 16; k++) {
        int idx = k * NTHREADS + tid;          // 0..16383
        int ry = idx >> 7;
        int rx = idx & 127;
        int gy = refl(gy0 + ry);
        int gx = refl(gx0 + rx);
        A[ry * STRIDE + rx] = g_Y[(size_t)gy * W + gx];
    }
    __syncthreads();

    // ---- stash center Y in registers (A gets overwritten later) ----
    float Yreg[9];
    #pragma unroll
    for (int k = 0; k < 9; k++) {
        int px = k * NTHREADS + tid;           // 0..9215
        int r = px / 96;
        int c = px - r * 96;
        Yreg[k] = A[(16 + r) * STRIDE + (16 + c)];
    }

    // ---- stage 1: horizontal box of Y and Y^2 (running sums) ----
    // 128 rows x 8 segments of 14 cols; valid output cols 8..119
    {
        int row = tid & 127, seg = tid >> 7;
        int c0 = 8 + seg * 14;
        const float* ar = A + row * STRIDE;
        float* br = B + row * STRIDE;
        float* cr2 = C + row * STRIDE;
        float s1 = 0.f, s2 = 0.f;
        #pragma unroll
        for (int k = -8; k <= 8; k++) { float v = ar[c0 + k]; s1 += v; s2 += v * v; }
        br[c0] = s1 * INV17; cr2[c0] = s2 * INV17;
        #pragma unroll
        for (int i = 1; i < 14; i++) {
            float vo = ar[c0 + i - 9], vn = ar[c0 + i + 8];
            s1 += vn - vo;
            s2 += vn * vn - vo * vo;
            br[c0 + i] = s1 * INV17; cr2[c0 + i] = s2 * INV17;
        }
    }
    __syncthreads();

    // ---- stage 3a: vertical box -> mean_I, mean_II -> a into A ----
    // cols 8..119 active x 8 segments of 14 rows; rows 8..119
    {
        int col = tid & 127, seg = tid >> 7;
        if (col >= 8 && col < 120) {
            int r0 = 8 + seg * 14;
            float s1 = 0.f, s2 = 0.f;
            #pragma unroll
            for (int k = -8; k <= 8; k++) {
                s1 += B[(r0 + k) * STRIDE + col];
                s2 += C[(r0 + k) * STRIDE + col];
            }
            #pragma unroll
            for (int i = 0; i < 14; i++) {
                int r = r0 + i;
                float mI = s1 * INV17, mII = s2 * INV17;
                float var = mII - mI * mI;
                float a = var / (var + EPSV);
                A[r * STRIDE + col] = a;
                if (i < 13) {
                    s1 += B[(r + 9) * STRIDE + col] - B[(r - 8) * STRIDE + col];
                    s2 += C[(r + 9) * STRIDE + col] - C[(r - 8) * STRIDE + col];
                }
            }
        }
    }
    __syncthreads();

    // ---- stage 3b: vertical box of B again -> b = mean_I - a*mean_I into C ----
    {
        int col = tid & 127, seg = tid >> 7;
        if (col >= 8 && col < 120) {
            int r0 = 8 + seg * 14;
            float s1 = 0.f;
            #pragma unroll
            for (int k = -8; k <= 8; k++) s1 += B[(r0 + k) * STRIDE + col];
            #pragma unroll
            for (int i = 0; i < 14; i++) {
                int r = r0 + i;
                float mI = s1 * INV17;
                float a = A[r * STRIDE + col];
                C[r * STRIDE + col] = mI - a * mI;
                if (i < 13)
                    s1 += B[(r + 9) * STRIDE + col] - B[(r - 8) * STRIDE + col];
            }
        }
    }
    __syncthreads();

    // ---- stage 4a: horizontal box of a (A) -> B; rows 8..119, cols 16..111 ----
    {
        int row = tid & 127, seg = tid >> 7;
        if (row >= 8 && row < 120) {
            int c0 = 16 + seg * 12;
            const float* ar = A + row * STRIDE;
            float* br = B + row * STRIDE;
            float s = 0.f;
            #pragma unroll
            for (int k = -8; k <= 8; k++) s += ar[c0 + k];
            #pragma unroll
            for (int i = 0; i < 12; i++) {
                br[c0 + i] = s * INV17;
                if (i < 11) s += ar[c0 + i + 9] - ar[c0 + i - 8];
            }
        }
    }
    __syncthreads();

    // ---- stage 4b: vertical box of B -> mean_a into A center ----
    {
        int col = tid & 127, seg = tid >> 7;
        if (col >= 16 && col < 112) {
            int r0 = 16 + seg * 12;
            float s = 0.f;
            #pragma unroll
            for (int k = -8; k <= 8; k++) s += B[(r0 + k) * STRIDE + col];
            #pragma unroll
            for (int i = 0; i < 12; i++) {
                A[(r0 + i) * STRIDE + col] = s * INV17;
                if (i < 11)
                    s += B[(r0 + i + 9) * STRIDE + col] - B[(r0 + i - 8) * STRIDE + col];
            }
        }
    }
    __syncthreads();

    // ---- stage 4c: horizontal box of b (C) -> B ----
    {
        int row = tid & 127, seg = tid >> 7;
        if (row >= 8 && row < 120) {
            int c0 = 16 + seg * 12;
            const float* cr2 = C + row * STRIDE;
            float* br = B + row * STRIDE;
            float s = 0.f;
            #pragma unroll
            for (int k = -8; k <= 8; k++) s += cr2[c0 + k];
            #pragma unroll
            for (int i = 0; i < 12; i++) {
                br[c0 + i] = s * INV17;
                if (i < 11) s += cr2[c0 + i + 9] - cr2[c0 + i - 8];
            }
        }
    }
    __syncthreads();

    // ---- stage 4d: vertical box of B -> mean_b into C center ----
    {
        int col = tid & 127, seg = tid >> 7;
        if (col >= 16 && col < 112) {
            int r0 = 16 + seg * 12;
            float s = 0.f;
            #pragma unroll
            for (int k = -8; k <= 8; k++) s += B[(r0 + k) * STRIDE + col];
            #pragma unroll
            for (int i = 0; i < 12; i++) {
                C[(r0 + i) * STRIDE + col] = s * INV17;
                if (i < 11)
                    s += B[(r0 + i + 9) * STRIDE + col] - B[(r0 + i - 8) * STRIDE + col];
            }
        }
    }
    __syncthreads();

    // ---- stage 5a: scale = (mean_a*Y + mean_b)/max(Y,1e-6) into A center ----
    #pragma unroll
    for (int k = 0; k < 9; k++) {
        int px = k * NTHREADS + tid;
        int r = px / 96;
        int c = px - r * 96;
        int off = (16 + r) * STRIDE + (16 + c);
        float ma = A[off];
        float mb = C[off];
        float y = Yreg[k];
        float s = (ma * y + mb) / fmaxf(y, 1e-6f);
        A[off] = s;
    }
    __syncthreads();

    // ---- stage 5b: apply to x, fully coalesced flat-float loop ----
    const int outy0 = blockIdx.y * T;
    const int outx0 = blockIdx.x * T;
    #pragma unroll
    for (int k = 0; k < 27; k++) {
        int f = k * NTHREADS + tid;            // 0..27647 (96*96*3)
        int r = f / 288;
        int rem = f - r * 288;
        int c = rem / 3;
        int ch = rem - c * 3;
        int gy = outy0 + r, gx = outx0 + c;
        if (gy < H && gx < W) {
            size_t addr = ((size_t)gy * W + gx) * 3 + ch;
            float s = A[(16 + r) * STRIDE + (16 + c)];
            float v = x[addr] * s;
            out[addr] = fminf(fmaxf(v, 0.f), 1.f);
        }
    }
}

// ---------------------------------------------------------------------------
extern "C" void kernel_launch(void* const* d_in, const int* in_sizes, int n_in,
                              void* d_out, int out_size) {
    const float* x = (const float*)d_in[0];
    float* out = (float*)d_out;

    const int smem_bytes = 3 * REGN * STRIDE * (int)sizeof(float);  // 198144
    cudaFuncSetAttribute(fused_kernel,
                         cudaFuncAttributeMaxDynamicSharedMemorySize, smem_bytes);

    // K1: luma (4 px / thread)
    luma_kernel<<<(H * W / 4) / 256, 256>>>(x);

    // K2: fused guided filter, 43x43 tiles of 96x96
    dim3 grid((W + T - 1) / T, (H + T - 1) / T);
    fused_kernel<<<grid, NTHREADS, smem_bytes>>>(x, out);
}

// round 6
// speedup vs baseline: 1.0034x; 1.0029x over previous
#include <cuda_runtime.h>

// Problem constants
#define H 4096
#define W 4096
#define EPSV 0.005f

// Tile config: 96x96 output, 128x128 halo region (radius 16 = 2 box filters of r=8)
#define T 96
#define REGN 128
#define STRIDE 129            // +1 pad: conflict-free row-strided access
#define NTHREADS 1024
#define INV17 (1.0f/17.0f)

// 64 MB luma scratch (device global: allocation-free per harness rules)
__device__ float g_Y[(size_t)H * W];

__device__ __forceinline__ int refl(int p) {
    p = (p < 0) ? -p : p;                 // 'reflect' mode: -1 -> 1
    return (p > H - 1) ? (2 * (H - 1) - p) : p;
}

// ---------------------------------------------------------------------------
// Kernel 1: Rec.709 luma, 4 pixels per thread via 3x float4 loads
// ---------------------------------------------------------------------------
__global__ void luma_kernel(const float* __restrict__ x) {
    int i = blockIdx.x * blockDim.x + threadIdx.x;   // quad-pixel index
    const float4* xv = (const float4*)x;
    float4 f0 = xv[3 * i + 0];
    float4 f1 = xv[3 * i + 1];
    float4 f2 = xv[3 * i + 2];
    const float cr = 0.2126f, cg = 0.7152f, cb = 0.0722f;
    float4 y;
    y.x = cr * f0.x + cg * f0.y + cb * f0.z;
    y.y = cr * f0.w + cg * f1.x + cb * f1.y;
    y.z = cr * f1.z + cg * f1.w + cb * f2.x;
    y.w = cr * f2.y + cg * f2.z + cb * f2.w;
    ((float4*)g_Y)[i] = y;
}

// ---------------------------------------------------------------------------
// Kernel 2: fully fused guided filter per 96x96 tile.
// Smem buffers (each 128x129 f32):
//   A: Y -> a -> mean_a -> scale
//   B: hbox(Y) -> hbox(a) -> hbox(b)
//   C: hbox(Y^2) -> b -> mean_b
// ---------------------------------------------------------------------------
__global__ void __launch_bounds__(NTHREADS, 1)
fused_kernel(const float* __restrict__ x, float* __restrict__ out) {
    extern __shared__ float smem[];
    float* A = smem;
    float* B = A + REGN * STRIDE;
    float* C = B + REGN * STRIDE;

    const int tid = threadIdx.x;
    const int gx0 = blockIdx.x * T - 16;
    const int gy0 = blockIdx.y * T - 16;

    // ---- stage 0: load Y halo (reflect-indexed), coalesced ----
    #pragma unroll
    for (int k = 0; k < 16; k++) {
        int idx = k * NTHREADS + tid;          // 0..16383
        int ry = idx >> 7;
        int rx = idx & 127;
        int gy = refl(gy0 + ry);
        int gx = refl(gx0 + rx);
        A[ry * STRIDE + rx] = g_Y[(size_t)gy * W + gx];
    }
    __syncthreads();

    // ---- stash center Y in registers (A gets overwritten later) ----
    float Yreg[9];
    #pragma unroll
    for (int k = 0; k < 9; k++) {
        int px = k * NTHREADS + tid;           // 0..9215
        int r = px / 96;
        int c = px - r * 96;
        Yreg[k] = A[(16 + r) * STRIDE + (16 + c)];
    }

    // ---- stage 1: horizontal box of Y and Y^2 (running sums) ----
    // 128 rows x 8 segments of 14 cols; valid output cols 8..119
    {
        int row = tid & 127, seg = tid >> 7;
        int c0 = 8 + seg * 14;
        const float* ar = A + row * STRIDE;
        float* br = B + row * STRIDE;
        float* cr2 = C + row * STRIDE;
        float s1 = 0.f, s2 = 0.f;
        #pragma unroll
        for (int k = -8; k <= 8; k++) { float v = ar[c0 + k]; s1 += v; s2 += v * v; }
        br[c0] = s1 * INV17; cr2[c0] = s2 * INV17;
        #pragma unroll
        for (int i = 1; i < 14; i++) {
            float vo = ar[c0 + i - 9], vn = ar[c0 + i + 8];
            s1 += vn - vo;
            s2 += vn * vn - vo * vo;
            br[c0 + i] = s1 * INV17; cr2[c0 + i] = s2 * INV17;
        }
    }
    __syncthreads();

    // ---- stage 3a: vertical box -> mean_I, mean_II -> a into A ----
    // cols 8..119 active x 8 segments of 14 rows; rows 8..119
    {
        int col = tid & 127, seg = tid >> 7;
        if (col >= 8 && col < 120) {
            int r0 = 8 + seg * 14;
            float s1 = 0.f, s2 = 0.f;
            #pragma unroll
            for (int k = -8; k <= 8; k++) {
                s1 += B[(r0 + k) * STRIDE + col];
                s2 += C[(r0 + k) * STRIDE + col];
            }
            #pragma unroll
            for (int i = 0; i < 14; i++) {
                int r = r0 + i;
                float mI = s1 * INV17, mII = s2 * INV17;
                float var = mII - mI * mI;
                float a = var / (var + EPSV);
                A[r * STRIDE + col] = a;
                if (i < 13) {
                    s1 += B[(r + 9) * STRIDE + col] - B[(r - 8) * STRIDE + col];
                    s2 += C[(r + 9) * STRIDE + col] - C[(r - 8) * STRIDE + col];
                }
            }
        }
    }
    __syncthreads();

    // ---- stage 3b: vertical box of B again -> b = mean_I - a*mean_I into C ----
    {
        int col = tid & 127, seg = tid >> 7;
        if (col >= 8 && col < 120) {
            int r0 = 8 + seg * 14;
            float s1 = 0.f;
            #pragma unroll
            for (int k = -8; k <= 8; k++) s1 += B[(r0 + k) * STRIDE + col];
            #pragma unroll
            for (int i = 0; i < 14; i++) {
                int r = r0 + i;
                float mI = s1 * INV17;
                float a = A[r * STRIDE + col];
                C[r * STRIDE + col] = mI - a * mI;
                if (i < 13)
                    s1 += B[(r + 9) * STRIDE + col] - B[(r - 8) * STRIDE + col];
            }
        }
    }
    __syncthreads();

    // ---- stage 4a: horizontal box of a (A) -> B; rows 8..119, cols 16..111 ----
    {
        int row = tid & 127, seg = tid >> 7;
        if (row >= 8 && row < 120) {
            int c0 = 16 + seg * 12;
            const float* ar = A + row * STRIDE;
            float* br = B + row * STRIDE;
            float s = 0.f;
            #pragma unroll
            for (int k = -8; k <= 8; k++) s += ar[c0 + k];
            #pragma unroll
            for (int i = 0; i < 12; i++) {
                br[c0 + i] = s * INV17;
                if (i < 11) s += ar[c0 + i + 9] - ar[c0 + i - 8];
            }
        }
    }
    __syncthreads();

    // ---- stage 4b: vertical box of B -> mean_a into A center ----
    {
        int col = tid & 127, seg = tid >> 7;
        if (col >= 16 && col < 112) {
            int r0 = 16 + seg * 12;
            float s = 0.f;
            #pragma unroll
            for (int k = -8; k <= 8; k++) s += B[(r0 + k) * STRIDE + col];
            #pragma unroll
            for (int i = 0; i < 12; i++) {
                A[(r0 + i) * STRIDE + col] = s * INV17;
                if (i < 11)
                    s += B[(r0 + i + 9) * STRIDE + col] - B[(r0 + i - 8) * STRIDE + col];
            }
        }
    }
    __syncthreads();

    // ---- stage 4c: horizontal box of b (C) -> B ----
    {
        int row = tid & 127, seg = tid >> 7;
        if (row >= 8 && row < 120) {
            int c0 = 16 + seg * 12;
            const float* cr2 = C + row * STRIDE;
            float* br = B + row * STRIDE;
            float s = 0.f;
            #pragma unroll
            for (int k = -8; k <= 8; k++) s += cr2[c0 + k];
            #pragma unroll
            for (int i = 0; i < 12; i++) {
                br[c0 + i] = s * INV17;
                if (i < 11) s += cr2[c0 + i + 9] - cr2[c0 + i - 8];
            }
        }
    }
    __syncthreads();

    // ---- stage 4d: vertical box of B -> mean_b into C center ----
    {
        int col = tid & 127, seg = tid >> 7;
        if (col >= 16 && col < 112) {
            int r0 = 16 + seg * 12;
            float s = 0.f;
            #pragma unroll
            for (int k = -8; k <= 8; k++) s += B[(r0 + k) * STRIDE + col];
            #pragma unroll
            for (int i = 0; i < 12; i++) {
                C[(r0 + i) * STRIDE + col] = s * INV17;
                if (i < 11)
                    s += B[(r0 + i + 9) * STRIDE + col] - B[(r0 + i - 8) * STRIDE + col];
            }
        }
    }
    __syncthreads();

    // ---- stage 5a: scale = (mean_a*Y + mean_b)/max(Y,1e-6) into A center ----
    #pragma unroll
    for (int k = 0; k < 9; k++) {
        int px = k * NTHREADS + tid;
        int r = px / 96;
        int c = px - r * 96;
        int off = (16 + r) * STRIDE + (16 + c);
        float ma = A[off];
        float mb = C[off];
        float y = Yreg[k];
        float s = (ma * y + mb) / fmaxf(y, 1e-6f);
        A[off] = s;
    }
    __syncthreads();

    // ---- stage 5b: apply to x, fully coalesced flat-float loop ----
    const int outy0 = blockIdx.y * T;
    const int outx0 = blockIdx.x * T;
    #pragma unroll
    for (int k = 0; k < 27; k++) {
        int f = k * NTHREADS + tid;            // 0..27647 (96*96*3)
        int r = f / 288;
        int rem = f - r * 288;
        int c = rem / 3;
        int ch = rem - c * 3;
        int gy = outy0 + r, gx = outx0 + c;
        if (gy < H && gx < W) {
            size_t addr = ((size_t)gy * W + gx) * 3 + ch;
            float s = A[(16 + r) * STRIDE + (16 + c)];
            float v = x[addr] * s;
            out[addr] = fminf(fmaxf(v, 0.f), 1.f);
        }
    }
}

// ---------------------------------------------------------------------------
extern "C" void kernel_launch(void* const* d_in, const int* in_sizes, int n_in,
                              void* d_out, int out_size) {
    const float* x = (const float*)d_in[0];
    float* out = (float*)d_out;

    const int smem_bytes = 3 * REGN * STRIDE * (int)sizeof(float);  // 198144
    cudaFuncSetAttribute(fused_kernel,
                         cudaFuncAttributeMaxDynamicSharedMemorySize, smem_bytes);

    // K1: luma (4 px / thread)
    luma_kernel<<<(H * W / 4) / 256, 256>>>(x);

    // K2: fused guided filter, 43x43 tiles of 96x96
    dim3 grid((W + T - 1) / T, (H + T - 1) / T);
    fused_kernel<<<grid, NTHREADS, smem_bytes>>>(x, out);
}